// round 9
// baseline (speedup 1.0000x reference)
#include <cuda_runtime.h>

#define HH    640
#define WW    640
#define BATCH 4
#define NLAB  10
#define NPIX  (HH*WW)
#define TILE_W 128
#define TILE_H 8
#define GXB (WW/TILE_W)            // 5
#define GYB (HH/TILE_H)            // 80
#define NBLOCKS (GXB*GYB*BATCH)    // 1600

__device__ float d_accIn[BATCH];
__device__ float d_accGrad[BATCH];
__device__ float d_boxF[BATCH*NLAB];
__device__ float d_boxE[BATCH*NLAB];
__device__ unsigned d_count;

__device__ __forceinline__ float wsum(float v) {
    #pragma unroll
    for (int o = 16; o; o >>= 1) v += __shfl_down_sync(0xffffffffu, v, o);
    return v;
}

struct G4 { float gx[4], gy[4], c[4]; };

// 1x4 sobel strip for one array: 3 aligned LDG.128 + 2 shuffles/row.
// Warp covers cols [c0base, c0base+128); lanes 0/31 patch tile edges with scalar LDG.
__device__ __forceinline__ G4 sobelG(const float* __restrict__ p, int base, int r,
                                     int c0, int lane)
{
    G4 o;
    float t1[3][4], t2[3][4];
    #pragma unroll
    for (int dr = 0; dr < 3; dr++) {
        int rr = r + dr - 1;
        bool in = (rr >= 0) & (rr < HH);              // warp-uniform
        const float* rowp = p + base + rr * WW;
        float4 q = make_float4(0.f, 0.f, 0.f, 0.f);
        if (in) q = *reinterpret_cast<const float4*>(rowp + c0);
        float pm1 = __shfl_up_sync(0xffffffffu, q.w, 1);
        float p4  = __shfl_down_sync(0xffffffffu, q.x, 1);
        if (lane == 0)  pm1 = (in && c0 > 0)       ? rowp[c0 - 1] : 0.f;
        if (lane == 31) p4  = (in && c0 + 4 < WW)  ? rowp[c0 + 4] : 0.f;
        t1[dr][0] = pm1 + 2.f*q.x + q.y;  t1[dr][1] = q.x + 2.f*q.y + q.z;
        t1[dr][2] = q.y + 2.f*q.z + q.w;  t1[dr][3] = q.z + 2.f*q.w + p4;
        t2[dr][0] = q.y - pm1; t2[dr][1] = q.z - q.x; t2[dr][2] = q.w - q.y; t2[dr][3] = p4 - q.z;
        if (dr == 1) { o.c[0] = q.x; o.c[1] = q.y; o.c[2] = q.z; o.c[3] = q.w; }
    }
    #pragma unroll
    for (int k = 0; k < 4; k++) {
        o.gx[k] = t2[0][k] + 2.f*t2[1][k] + t2[2][k];
        o.gy[k] = t1[0][k] - t1[2][k];
    }
    return o;
}

// Exact masked 3x3 sobel F at a box-ring pixel (global reads; L1-hot).
__device__ float maskedF_g(const float* __restrict__ vis, const float* __restrict__ th,
                           const float* __restrict__ gen, int base, int r, int c, int4 B)
{
    float v[8], t[8], g[8];
    const int dr[8] = {-1,-1,-1, 0, 0, 1, 1, 1};
    const int dc[8] = {-1, 0, 1,-1, 1,-1, 0, 1};
    #pragma unroll
    for (int i = 0; i < 8; i++) {
        int rr = r + dr[i], cc = c + dc[i];
        bool in = (rr >= B.y) & (rr < B.w) & (cc >= B.x) & (cc < B.z);
        int q = in ? base + rr * WW + cc : base;
        float m = in ? 1.f : 0.f;
        v[i] = vis[q] * m; t[i] = th[q] * m; g[i] = gen[q] * m;
    }
    float gxV = (v[2]-v[0]) + 2.f*(v[4]-v[3]) + (v[7]-v[5]);
    float gyV = (v[0]-v[5]) + 2.f*(v[1]-v[6]) + (v[2]-v[7]);
    float gxT = (t[2]-t[0]) + 2.f*(t[4]-t[3]) + (t[7]-t[5]);
    float gyT = (t[0]-t[5]) + 2.f*(t[1]-t[6]) + (t[2]-t[7]);
    float gxG = (g[2]-g[0]) + 2.f*(g[4]-g[3]) + (g[7]-g[5]);
    float gyG = (g[0]-g[5]) + 2.f*(g[1]-g[6]) + (g[2]-g[7]);
    float gradV = fabsf(gxV) + fabsf(gyV);
    float g7 = fabsf(0.3f*gxV + 0.7f*gxT) + fabsf(0.3f*gyV + 0.7f*gyT);
    float gradG = fabsf(gxG) + fabsf(gyG);
    return fabsf(gradG - fmaxf(gradV, g7));
}

__global__ __launch_bounds__(256) void fused_k(
    const float* __restrict__ vis, const float* __restrict__ th,
    const float* __restrict__ gen, const int* __restrict__ label,
    const float* __restrict__ bptr, const float* __restrict__ cptr,
    float* __restrict__ out)
{
    __shared__ float redIn[8], redGr[8];
    __shared__ int   sIsLast;
    __shared__ float sLs[BATCH*NLAB], sL1[BATCH*NLAB];

    const int lane = threadIdx.x, ty = threadIdx.y;
    const int tid = ty * 32 + lane;
    const int bz = blockIdx.z;
    const int colStart = blockIdx.x * TILE_W;
    const int rowStart = blockIdx.y * TILE_H;
    const int r  = rowStart + ty;
    const int c0 = colStart + lane * 4;
    const int base = bz * NPIX;

    // Stencils straight from global (L1 serves vertical re-reads)
    G4 gv = sobelG(vis, base, r, c0, lane);
    G4 gt = sobelG(th , base, r, c0, lane);
    G4 gg = sobelG(gen, base, r, c0, lane);

    float li = 0.f, lg = 0.f;
    #pragma unroll
    for (int k = 0; k < 4; k++) {
        float gradV = fabsf(gv.gx[k]) + fabsf(gv.gy[k]);
        float gradG = fabsf(gg.gx[k]) + fabsf(gg.gy[k]);
        float g5 = 0.5f * (fabsf(gv.gx[k] + gt.gx[k]) + fabsf(gv.gy[k] + gt.gy[k]));
        float xm = 0.5f * (gv.c[k] + gt.c[k]);
        li += fabsf(gg.c[k] - fmaxf(gv.c[k], xm));
        lg += fabsf(gradG - fmaxf(gradV, g5));
    }

    // Warp-private box list via ballot + shuffle broadcast (no smem, no barrier)
    {
        int4 myB = make_int4(0, 0, 0, 0);
        bool ov = false;
        if (lane < NLAB) {
            const int* L = label + (bz * NLAB + lane) * 5;
            int x1 = L[1], y1 = L[2], x2 = L[3], y2 = L[4];
            myB = make_int4(x1, y1, x2, y2);
            ov = (x2 > x1) && (y2 > y1) &&
                 (x1 < colStart + TILE_W) && (x2 > colStart) &&
                 (y1 < rowStart + TILE_H) && (y2 > rowStart);
        }
        unsigned mask = __ballot_sync(0xffffffffu, ov);
        if (mask) {
            float F[4], E[4];
            #pragma unroll
            for (int k = 0; k < 4; k++) {
                float gradV = fabsf(gv.gx[k]) + fabsf(gv.gy[k]);
                float gradG = fabsf(gg.gx[k]) + fabsf(gg.gy[k]);
                float g7 = fabsf(0.3f*gv.gx[k] + 0.7f*gt.gx[k]) + fabsf(0.3f*gv.gy[k] + 0.7f*gt.gy[k]);
                float xm7 = 0.3f * gv.c[k] + 0.7f * gt.c[k];
                F[k] = fabsf(gradG - fmaxf(gradV, g7));
                E[k] = fabsf(gg.c[k] - fmaxf(gv.c[k], xm7));
            }
            while (mask) {
                int src = __ffs(mask) - 1;
                mask &= mask - 1;
                int4 B;
                B.x = __shfl_sync(0xffffffffu, myB.x, src);
                B.y = __shfl_sync(0xffffffffu, myB.y, src);
                B.z = __shfl_sync(0xffffffffu, myB.z, src);
                B.w = __shfl_sync(0xffffffffu, myB.w, src);
                float fb = 0.f, eb = 0.f;
                if (r >= B.y && r < B.w) {
                    bool rowInt = (r > B.y) & (r < B.w - 1);
                    #pragma unroll
                    for (int k = 0; k < 4; k++) {
                        int c = c0 + k;
                        if (c >= B.x && c < B.z) {
                            eb += E[k];
                            if (rowInt && c > B.x && c < B.z - 1) fb += F[k];
                            else fb += maskedF_g(vis, th, gen, base, r, c, B);
                        }
                    }
                }
                fb = wsum(fb); eb = wsum(eb);
                if (lane == 0) {
                    atomicAdd(&d_boxF[bz * NLAB + src], fb);
                    atomicAdd(&d_boxE[bz * NLAB + src], eb);
                }
            }
        }
    }

    // Block-staged li/lg reduce (ONE global atomic per block per counter)
    li = wsum(li); lg = wsum(lg);
    if (lane == 0) { redIn[ty] = li; redGr[ty] = lg; }
    __syncthreads();
    if (tid == 0) {
        float a = 0.f, bb = 0.f;
        #pragma unroll
        for (int i = 0; i < 8; i++) { a += redIn[i]; bb += redGr[i]; }
        atomicAdd(&d_accIn[bz],  a);
        atomicAdd(&d_accGrad[bz], bb);
    }

    // Last-block finalize
    __threadfence();
    __syncthreads();
    if (tid == 0) {
        unsigned o = atomicAdd(&d_count, 1u);
        sIsLast = (o == NBLOCKS - 1);
    }
    __syncthreads();
    if (!sIsLast) return;

    if (tid < BATCH * NLAB) {
        const int* L = label + tid * 5;
        int x1 = L[1], y1 = L[2], x2 = L[3], y2 = L[4];
        bool valid = !(x1 == 0 && y1 == 0 && x2 == 0 && y2 == 0);
        float area = (float)((y2 - y1) * (x2 - x1));       // C == 1
        float sa = fmaxf(area, 1.f);
        volatile float* vF = (volatile float*)d_boxF;
        volatile float* vE = (volatile float*)d_boxE;
        float f = vF[tid], e = vE[tid];
        float vv = valid ? 1.f : 0.f;
        sLs[tid] = (f / sa) * vv;
        sL1[tid] = (e / sa) * vv;
        d_boxF[tid] = 0.f; d_boxE[tid] = 0.f;              // reset for next replay
    }
    __syncthreads();
    if (tid < BATCH) {
        volatile float* aI = (volatile float*)d_accIn;
        volatile float* aG = (volatile float*)d_accGrad;
        const float inv = 1.0f / (float)NPIX;              // C == 1
        float loss_in   = aI[tid] * inv;
        float loss_grad = aG[tid] * inv;
        d_accIn[tid] = 0.f; d_accGrad[tid] = 0.f;          // reset

        float sLsum = 0.f, s1sum = 0.f, cnt = 0.f;
        for (int n = 0; n < NLAB; n++) {
            float a = sLs[tid * NLAB + n], bb = sL1[tid * NLAB + n];
            sLsum += a; s1sum += bb;
            if (a != 0.f || bb != 0.f) cnt += 1.f;
        }
        float safe_cnt = fmaxf(cnt, 1.f);
        float ls  = (cnt > 0.f) ? sLsum / safe_cnt : 0.f;
        float lin = (cnt > 0.f) ? s1sum / safe_cnt : 0.f;
        float alpha = *bptr, beta = *cptr;
        out[0*BATCH + tid] = 0.f;                                         // loss_ss
        out[1*BATCH + tid] = alpha * loss_in + (1.f - alpha) * loss_grad; // loss_global
        out[2*BATCH + tid] = (1.f - beta) * ls + beta * lin;              // loss_label
        out[3*BATCH + tid] = loss_in;
        out[4*BATCH + tid] = loss_grad;
        out[5*BATCH + tid] = ls;
        out[6*BATCH + tid] = lin;
    }
    if (tid == 0) d_count = 0;                                            // reset
}

extern "C" void kernel_launch(void* const* d_in, const int* in_sizes, int n_in,
                              void* d_out, int out_size)
{
    (void)in_sizes; (void)n_in; (void)out_size;
    const float* bptr  = (const float*)d_in[0];
    const float* cptr  = (const float*)d_in[1];
    const float* vis   = (const float*)d_in[2];
    // d_in[3] = image_ir (unused by the reference)
    const float* gen   = (const float*)d_in[4];
    const int*   label = (const int*)d_in[5];
    const float* th    = (const float*)d_in[6];
    float* out = (float*)d_out;

    dim3 grid(GXB, GYB, BATCH);
    dim3 blk(32, 8);
    fused_k<<<grid, blk>>>(vis, th, gen, label, bptr, cptr, out);
}

// round 10
// speedup vs baseline: 1.4747x; 1.4747x over previous
#include <cuda_runtime.h>
#include <cstdint>

#define HH    640
#define WW    640
#define BATCH 4
#define NLAB  10
#define NPIX  (HH*WW)
#define TILE_W 128
#define TILE_H 8
#define GXB (WW/TILE_W)            // 5
#define GYB (HH/TILE_H)            // 80
#define NBLOCKS (GXB*GYB*BATCH)    // 1600
#define SMW 136                    // smem row width (floats): 4 left halo + 128 + 1 right (+pad). 544B, 16B-aligned rows.
#define HROWS (TILE_H+2)           // 10
#define ITEMS_PER_ARR (HROWS*34)   // 340 float4 items
#define ITEMS_TOTAL (3*ITEMS_PER_ARR) // 1020

__device__ float d_accIn[BATCH];
__device__ float d_accGrad[BATCH];
__device__ float d_boxF[BATCH*NLAB];
__device__ float d_boxE[BATCH*NLAB];
__device__ unsigned d_count;

__device__ __forceinline__ float wsum(float v) {
    #pragma unroll
    for (int o = 16; o; o >>= 1) v += __shfl_down_sync(0xffffffffu, v, o);
    return v;
}

__device__ __forceinline__ void cpasync16(uint32_t saddr, const float* g, bool pred) {
    int sz = pred ? 16 : 0;
    asm volatile("cp.async.ca.shared.global [%0], [%1], 16, %2;\n"
                 :: "r"(saddr), "l"(g), "r"(sz));
}

struct G4 { float gx[4], gy[4], c[4]; };

// Separable sobel for a 1x4 strip. Center pixel k at smem col 4tx+4+k.
__device__ __forceinline__ G4 sobel4(const float sm[HROWS][SMW], int ty, int tx) {
    G4 o;
    float t1[3][4], t2[3][4];
    #pragma unroll
    for (int r = 0; r < 3; r++) {
        const float* row = &sm[ty + r][0];
        float2 L = *reinterpret_cast<const float2*>(row + 4*tx + 2);
        float4 M = *reinterpret_cast<const float4*>(row + 4*tx + 4);
        float2 R = *reinterpret_cast<const float2*>(row + 4*tx + 8);
        float pm1 = L.y, p0 = M.x, p1 = M.y, p2 = M.z, p3 = M.w, p4 = R.x;
        t1[r][0] = pm1 + 2.f*p0 + p1;  t1[r][1] = p0 + 2.f*p1 + p2;
        t1[r][2] = p1 + 2.f*p2 + p3;   t1[r][3] = p2 + 2.f*p3 + p4;
        t2[r][0] = p1 - pm1;  t2[r][1] = p2 - p0;  t2[r][2] = p3 - p1;  t2[r][3] = p4 - p2;
        if (r == 1) { o.c[0] = p0; o.c[1] = p1; o.c[2] = p2; o.c[3] = p3; }
    }
    #pragma unroll
    for (int k = 0; k < 4; k++) {
        o.gx[k] = t2[0][k] + 2.f*t2[1][k] + t2[2][k];
        o.gy[k] = t1[0][k] - t1[2][k];
    }
    return o;
}

// Exact masked sobel F at a ring pixel from the shared tiles. lcc = 4tx+4+k.
__device__ float maskedF(const float sV[HROWS][SMW], const float sT[HROWS][SMW],
                         const float sG[HROWS][SMW], int ty, int lcc,
                         int r, int c, int4 B)
{
    const float wx[3][3] = {{-1,0,1},{-2,0,2},{-1,0,1}};
    const float wy[3][3] = {{1,2,1},{0,0,0},{-1,-2,-1}};
    float gxV=0,gyV=0,gxT=0,gyT=0,gxG=0,gyG=0;
    #pragma unroll
    for (int dr = 0; dr < 3; dr++)
    #pragma unroll
    for (int dc = 0; dc < 3; dc++) {
        int rr = r + dr - 1, cc = c + dc - 1;
        bool in = (rr >= B.y) & (rr < B.w) & (cc >= B.x) & (cc < B.z);
        float m = in ? 1.f : 0.f;
        float fv = sV[ty + dr][lcc - 1 + dc] * m;
        float ft = sT[ty + dr][lcc - 1 + dc] * m;
        float fg = sG[ty + dr][lcc - 1 + dc] * m;
        gxV += wx[dr][dc] * fv; gyV += wy[dr][dc] * fv;
        gxT += wx[dr][dc] * ft; gyT += wy[dr][dc] * ft;
        gxG += wx[dr][dc] * fg; gyG += wy[dr][dc] * fg;
    }
    float gradV = fabsf(gxV) + fabsf(gyV);
    float grad7 = fabsf(0.3f*gxV + 0.7f*gxT) + fabsf(0.3f*gyV + 0.7f*gyT);
    float gradG = fabsf(gxG) + fabsf(gyG);
    return fabsf(gradG - fmaxf(gradV, grad7));
}

__global__ __launch_bounds__(256) void fused_k(
    const float* __restrict__ vis, const float* __restrict__ th,
    const float* __restrict__ gen, const int* __restrict__ label,
    const float* __restrict__ bptr, const float* __restrict__ cptr,
    float* __restrict__ out)
{
    __shared__ __align__(16) float sAll[3][HROWS][SMW];
    __shared__ int4  sBox[NLAB];
    __shared__ int   sBoxIdx[NLAB];
    __shared__ float sAF[NLAB], sAE[NLAB];
    __shared__ int   sN;
    __shared__ float redIn[8], redGr[8];
    __shared__ int   sIsLast;
    __shared__ float sLs[BATCH*NLAB], sL1[BATCH*NLAB];

    const int tx = threadIdx.x, ty = threadIdx.y;
    const int tid = ty * 32 + tx;
    const int bz = blockIdx.z;
    const int colStart = blockIdx.x * TILE_W;
    const int rowStart = blockIdx.y * TILE_H;
    const int base = bz * NPIX;

    const float* arrs[3] = { vis, th, gen };

    // Async halo: 1020 aligned 16B copies (zero-fill outside the image).
    #pragma unroll
    for (int s = 0; s < 4; s++) {
        int item = tid + 256 * s;
        if (item < ITEMS_TOTAL) {
            int arr = item / ITEMS_PER_ARR;
            int rem = item - arr * ITEMS_PER_ARR;
            int lr = rem / 34, j = rem - lr * 34;
            int gr = rowStart - 1 + lr;
            int gc0 = colStart - 4 + 4 * j;
            bool in = (gr >= 0) & (gr < HH) & (gc0 >= 0) & (gc0 < WW);
            const float* g = arrs[arr] + (in ? base + gr * WW + gc0 : base);
            uint32_t sa = (uint32_t)__cvta_generic_to_shared(&sAll[arr][lr][4 * j]);
            cpasync16(sa, g, in);
        }
    }
    asm volatile("cp.async.commit_group;\n");

    // Warp 0 builds the overlapping-box list while copies are in flight.
    if (tid < 32) {
        if (tid == 0) sN = 0;
        if (tid < NLAB) { sAF[tid] = 0.f; sAE[tid] = 0.f; }
        __syncwarp();
        if (tid < NLAB) {
            const int* L = label + (bz * NLAB + tid) * 5;
            int x1 = L[1], y1 = L[2], x2 = L[3], y2 = L[4];
            if (x2 > x1 && y2 > y1 &&
                x1 < colStart + TILE_W && x2 > colStart &&
                y1 < rowStart + TILE_H && y2 > rowStart) {
                int p = atomicAdd(&sN, 1);
                sBox[p] = make_int4(x1, y1, x2, y2);
                sBoxIdx[p] = bz * NLAB + tid;
            }
        }
    }

    asm volatile("cp.async.wait_group 0;\n");
    __syncthreads();
    const int nOv = sN;

    typedef const float (*Tile)[SMW];
    Tile sV = sAll[0], sT = sAll[1], sG = sAll[2];

    G4 gv = sobel4(sAll[0], ty, tx);
    G4 gt = sobel4(sAll[1], ty, tx);
    G4 gg = sobel4(sAll[2], ty, tx);

    float li = 0.f, lg = 0.f;
    #pragma unroll
    for (int k = 0; k < 4; k++) {
        float gradV = fabsf(gv.gx[k]) + fabsf(gv.gy[k]);
        float gradG = fabsf(gg.gx[k]) + fabsf(gg.gy[k]);
        float g5 = 0.5f * (fabsf(gv.gx[k] + gt.gx[k]) + fabsf(gv.gy[k] + gt.gy[k]));
        float xm = 0.5f * (gv.c[k] + gt.c[k]);
        li += fabsf(gg.c[k] - fmaxf(gv.c[k], xm));
        lg += fabsf(gradG - fmaxf(gradV, g5));
    }

    if (nOv > 0) {
        float F[4], E[4];
        #pragma unroll
        for (int k = 0; k < 4; k++) {
            float gradV = fabsf(gv.gx[k]) + fabsf(gv.gy[k]);
            float gradG = fabsf(gg.gx[k]) + fabsf(gg.gy[k]);
            float g7 = fabsf(0.3f*gv.gx[k] + 0.7f*gt.gx[k]) + fabsf(0.3f*gv.gy[k] + 0.7f*gt.gy[k]);
            float xm7 = 0.3f * gv.c[k] + 0.7f * gt.c[k];
            F[k] = fabsf(gradG - fmaxf(gradV, g7));
            E[k] = fabsf(gg.c[k] - fmaxf(gv.c[k], xm7));
        }
        const int r = rowStart + ty;
        const int cbase = colStart + tx * 4;
        for (int b = 0; b < nOv; b++) {
            int4 B = sBox[b];
            float fb = 0.f, eb = 0.f;
            if (r >= B.y && r < B.w) {
                bool rowInt = (r > B.y) & (r < B.w - 1);
                #pragma unroll
                for (int k = 0; k < 4; k++) {
                    int c = cbase + k;
                    if (c >= B.x && c < B.z) {
                        eb += E[k];
                        if (rowInt && c > B.x && c < B.z - 1) fb += F[k];
                        else fb += maskedF(sV, sT, sG, ty, 4*tx + 4 + k, r, c, B);
                    }
                }
            }
            fb = wsum(fb); eb = wsum(eb);
            if (tx == 0) { atomicAdd(&sAF[b], fb); atomicAdd(&sAE[b], eb); }
        }
    }

    // Block-staged li/lg reduce: ONE global atomic per block per counter.
    li = wsum(li); lg = wsum(lg);
    if (tx == 0) { redIn[ty] = li; redGr[ty] = lg; }
    __syncthreads();
    if (tid == 0) {
        float a = 0.f, bb = 0.f;
        #pragma unroll
        for (int i = 0; i < 8; i++) { a += redIn[i]; bb += redGr[i]; }
        atomicAdd(&d_accIn[bz],  a);
        atomicAdd(&d_accGrad[bz], bb);
    }
    if (tid < nOv) {
        atomicAdd(&d_boxF[sBoxIdx[tid]], sAF[tid]);
        atomicAdd(&d_boxE[sBoxIdx[tid]], sAE[tid]);
    }

    // Last-block finalize
    __threadfence();
    __syncthreads();
    if (tid == 0) {
        unsigned o = atomicAdd(&d_count, 1u);
        sIsLast = (o == NBLOCKS - 1);
    }
    __syncthreads();
    if (!sIsLast) return;

    if (tid < BATCH * NLAB) {
        const int* L = label + tid * 5;
        int x1 = L[1], y1 = L[2], x2 = L[3], y2 = L[4];
        bool valid = !(x1 == 0 && y1 == 0 && x2 == 0 && y2 == 0);
        float area = (float)((y2 - y1) * (x2 - x1));       // C == 1
        float sa = fmaxf(area, 1.f);
        volatile float* vF = (volatile float*)d_boxF;
        volatile float* vE = (volatile float*)d_boxE;
        float f = vF[tid], e = vE[tid];
        float vv = valid ? 1.f : 0.f;
        sLs[tid] = (f / sa) * vv;
        sL1[tid] = (e / sa) * vv;
        d_boxF[tid] = 0.f; d_boxE[tid] = 0.f;              // reset for next replay
    }
    __syncthreads();
    if (tid < BATCH) {
        volatile float* aI = (volatile float*)d_accIn;
        volatile float* aG = (volatile float*)d_accGrad;
        const float inv = 1.0f / (float)NPIX;              // C == 1
        float loss_in   = aI[tid] * inv;
        float loss_grad = aG[tid] * inv;
        d_accIn[tid] = 0.f; d_accGrad[tid] = 0.f;          // reset

        float sLsum = 0.f, s1sum = 0.f, cnt = 0.f;
        for (int n = 0; n < NLAB; n++) {
            float a = sLs[tid * NLAB + n], bb = sL1[tid * NLAB + n];
            sLsum += a; s1sum += bb;
            if (a != 0.f || bb != 0.f) cnt += 1.f;
        }
        float safe_cnt = fmaxf(cnt, 1.f);
        float ls  = (cnt > 0.f) ? sLsum / safe_cnt : 0.f;
        float lin = (cnt > 0.f) ? s1sum / safe_cnt : 0.f;
        float alpha = *bptr, beta = *cptr;
        out[0*BATCH + tid] = 0.f;                                         // loss_ss
        out[1*BATCH + tid] = alpha * loss_in + (1.f - alpha) * loss_grad; // loss_global
        out[2*BATCH + tid] = (1.f - beta) * ls + beta * lin;              // loss_label
        out[3*BATCH + tid] = loss_in;
        out[4*BATCH + tid] = loss_grad;
        out[5*BATCH + tid] = ls;
        out[6*BATCH + tid] = lin;
    }
    if (tid == 0) d_count = 0;                                            // reset
}

extern "C" void kernel_launch(void* const* d_in, const int* in_sizes, int n_in,
                              void* d_out, int out_size)
{
    (void)in_sizes; (void)n_in; (void)out_size;
    const float* bptr  = (const float*)d_in[0];
    const float* cptr  = (const float*)d_in[1];
    const float* vis   = (const float*)d_in[2];
    // d_in[3] = image_ir (unused by the reference)
    const float* gen   = (const float*)d_in[4];
    const int*   label = (const int*)d_in[5];
    const float* th    = (const float*)d_in[6];
    float* out = (float*)d_out;

    dim3 grid(GXB, GYB, BATCH);
    dim3 blk(32, 8);
    fused_k<<<grid, blk>>>(vis, th, gen, label, bptr, cptr, out);
}

// round 11
// speedup vs baseline: 1.4898x; 1.0102x over previous
#include <cuda_runtime.h>
#include <cstdint>

#define HH    640
#define WW    640
#define BATCH 4
#define NLAB  10
#define NPIX  (HH*WW)
#define TILE_W 128
#define TILE_H 8
#define GXB (WW/TILE_W)            // 5
#define GYB (HH/TILE_H)            // 80
#define NBLOCKS (GXB*GYB*BATCH)    // 1600
#define SMW 136                    // smem row width (floats): 4 left halo + 128 + 1 right (+pad); rows 16B-aligned
#define HROWS (TILE_H+2)           // 10
#define ITEMS_PER_ARR (HROWS*34)   // 340 float4 items
#define ITEMS_TOTAL (3*ITEMS_PER_ARR) // 1020

__device__ float d_accIn[BATCH];
__device__ float d_accGrad[BATCH];
__device__ float d_boxF[BATCH*NLAB];
__device__ float d_boxE[BATCH*NLAB];
__device__ unsigned d_count;

__device__ __forceinline__ float wsum(float v) {
    #pragma unroll
    for (int o = 16; o; o >>= 1) v += __shfl_down_sync(0xffffffffu, v, o);
    return v;
}

__device__ __forceinline__ void cpasync16(uint32_t saddr, const float* g, bool pred) {
    int sz = pred ? 16 : 0;
    asm volatile("cp.async.ca.shared.global [%0], [%1], 16, %2;\n"
                 :: "r"(saddr), "l"(g), "r"(sz));
}

struct G4 { float gx[4], gy[4], c[4]; };

// Separable sobel, 6 live values per row: scalar LDS for pm1/p4, aligned LDS.128 for p0..p3.
// Center pixel k of thread tx lives at smem col 4tx+4+k.
__device__ __forceinline__ G4 sobel4(const float sm[HROWS][SMW], int ty, int tx) {
    G4 o;
    float t1[3][4], t2[3][4];
    #pragma unroll
    for (int r = 0; r < 3; r++) {
        const float* row = &sm[ty + r][0];
        float  pm1 = row[4*tx + 3];                                  // LDS.32, conflict-free
        float4 M   = *reinterpret_cast<const float4*>(row + 4*tx + 4); // LDS.128 aligned
        float  p4  = row[4*tx + 8];                                  // LDS.32, conflict-free
        float p0 = M.x, p1 = M.y, p2 = M.z, p3 = M.w;
        t1[r][0] = pm1 + 2.f*p0 + p1;  t1[r][1] = p0 + 2.f*p1 + p2;
        t1[r][2] = p1 + 2.f*p2 + p3;   t1[r][3] = p2 + 2.f*p3 + p4;
        t2[r][0] = p1 - pm1;  t2[r][1] = p2 - p0;  t2[r][2] = p3 - p1;  t2[r][3] = p4 - p2;
        if (r == 1) { o.c[0] = p0; o.c[1] = p1; o.c[2] = p2; o.c[3] = p3; }
    }
    #pragma unroll
    for (int k = 0; k < 4; k++) {
        o.gx[k] = t2[0][k] + 2.f*t2[1][k] + t2[2][k];
        o.gy[k] = t1[0][k] - t1[2][k];
    }
    return o;
}

// Exact masked sobel F at a ring pixel from the shared tiles. lcc = 4tx+4+k.
__device__ float maskedF(const float sV[HROWS][SMW], const float sT[HROWS][SMW],
                         const float sG[HROWS][SMW], int ty, int lcc,
                         int r, int c, int4 B)
{
    const float wx[3][3] = {{-1,0,1},{-2,0,2},{-1,0,1}};
    const float wy[3][3] = {{1,2,1},{0,0,0},{-1,-2,-1}};
    float gxV=0,gyV=0,gxT=0,gyT=0,gxG=0,gyG=0;
    #pragma unroll
    for (int dr = 0; dr < 3; dr++)
    #pragma unroll
    for (int dc = 0; dc < 3; dc++) {
        int rr = r + dr - 1, cc = c + dc - 1;
        bool in = (rr >= B.y) & (rr < B.w) & (cc >= B.x) & (cc < B.z);
        float m = in ? 1.f : 0.f;
        float fv = sV[ty + dr][lcc - 1 + dc] * m;
        float ft = sT[ty + dr][lcc - 1 + dc] * m;
        float fg = sG[ty + dr][lcc - 1 + dc] * m;
        gxV += wx[dr][dc] * fv; gyV += wy[dr][dc] * fv;
        gxT += wx[dr][dc] * ft; gyT += wy[dr][dc] * ft;
        gxG += wx[dr][dc] * fg; gyG += wy[dr][dc] * fg;
    }
    float gradV = fabsf(gxV) + fabsf(gyV);
    float grad7 = fabsf(0.3f*gxV + 0.7f*gxT) + fabsf(0.3f*gyV + 0.7f*gyT);
    float gradG = fabsf(gxG) + fabsf(gyG);
    return fabsf(gradG - fmaxf(gradV, grad7));
}

__global__ __launch_bounds__(256) void fused_k(
    const float* __restrict__ vis, const float* __restrict__ th,
    const float* __restrict__ gen, const int* __restrict__ label,
    const float* __restrict__ bptr, const float* __restrict__ cptr,
    float* __restrict__ out)
{
    __shared__ __align__(16) float sAll[3][HROWS][SMW];
    __shared__ int4  sBox[NLAB];
    __shared__ int   sBoxIdx[NLAB];
    __shared__ float sAF[NLAB], sAE[NLAB];
    __shared__ int   sN;
    __shared__ float redIn[8], redGr[8];
    __shared__ int   sIsLast;
    __shared__ float sLs[BATCH*NLAB], sL1[BATCH*NLAB];

    const int tx = threadIdx.x, ty = threadIdx.y;
    const int tid = ty * 32 + tx;
    const int bz = blockIdx.z;
    const int colStart = blockIdx.x * TILE_W;
    const int rowStart = blockIdx.y * TILE_H;
    const int base = bz * NPIX;

    const float* arrs[3] = { vis, th, gen };

    // Async halo: 1020 aligned 16B copies (zero-fill outside the image).
    #pragma unroll
    for (int s = 0; s < 4; s++) {
        int item = tid + 256 * s;
        if (item < ITEMS_TOTAL) {
            int arr = item / ITEMS_PER_ARR;
            int rem = item - arr * ITEMS_PER_ARR;
            int lr = rem / 34, j = rem - lr * 34;
            int gr = rowStart - 1 + lr;
            int gc0 = colStart - 4 + 4 * j;
            bool in = (gr >= 0) & (gr < HH) & (gc0 >= 0) & (gc0 < WW);
            const float* g = arrs[arr] + (in ? base + gr * WW + gc0 : base);
            uint32_t sa = (uint32_t)__cvta_generic_to_shared(&sAll[arr][lr][4 * j]);
            cpasync16(sa, g, in);
        }
    }
    asm volatile("cp.async.commit_group;\n");

    // Warp 0 builds the overlapping-box list while copies are in flight.
    if (tid < 32) {
        if (tid == 0) sN = 0;
        if (tid < NLAB) { sAF[tid] = 0.f; sAE[tid] = 0.f; }
        __syncwarp();
        if (tid < NLAB) {
            const int* L = label + (bz * NLAB + tid) * 5;
            int x1 = L[1], y1 = L[2], x2 = L[3], y2 = L[4];
            if (x2 > x1 && y2 > y1 &&
                x1 < colStart + TILE_W && x2 > colStart &&
                y1 < rowStart + TILE_H && y2 > rowStart) {
                int p = atomicAdd(&sN, 1);
                sBox[p] = make_int4(x1, y1, x2, y2);
                sBoxIdx[p] = bz * NLAB + tid;
            }
        }
    }

    asm volatile("cp.async.wait_group 0;\n");
    __syncthreads();
    const int nOv = sN;

    typedef const float (*Tile)[SMW];
    Tile sV = sAll[0], sT = sAll[1], sG = sAll[2];

    G4 gv = sobel4(sAll[0], ty, tx);
    G4 gt = sobel4(sAll[1], ty, tx);
    G4 gg = sobel4(sAll[2], ty, tx);

    float li = 0.f, lg = 0.f;
    #pragma unroll
    for (int k = 0; k < 4; k++) {
        float gradV = fabsf(gv.gx[k]) + fabsf(gv.gy[k]);
        float gradG = fabsf(gg.gx[k]) + fabsf(gg.gy[k]);
        float g5 = 0.5f * (fabsf(gv.gx[k] + gt.gx[k]) + fabsf(gv.gy[k] + gt.gy[k]));
        float xm = 0.5f * (gv.c[k] + gt.c[k]);
        li += fabsf(gg.c[k] - fmaxf(gv.c[k], xm));
        lg += fabsf(gradG - fmaxf(gradV, g5));
    }

    if (nOv > 0) {
        float F[4], E[4];
        #pragma unroll
        for (int k = 0; k < 4; k++) {
            float gradV = fabsf(gv.gx[k]) + fabsf(gv.gy[k]);
            float gradG = fabsf(gg.gx[k]) + fabsf(gg.gy[k]);
            float g7 = fabsf(0.3f*gv.gx[k] + 0.7f*gt.gx[k]) + fabsf(0.3f*gv.gy[k] + 0.7f*gt.gy[k]);
            float xm7 = 0.3f * gv.c[k] + 0.7f * gt.c[k];
            F[k] = fabsf(gradG - fmaxf(gradV, g7));
            E[k] = fabsf(gg.c[k] - fmaxf(gv.c[k], xm7));
        }
        const int r = rowStart + ty;
        const int cbase = colStart + tx * 4;
        for (int b = 0; b < nOv; b++) {
            int4 B = sBox[b];
            float fb = 0.f, eb = 0.f;
            if (r >= B.y && r < B.w) {
                bool rowInt = (r > B.y) & (r < B.w - 1);
                #pragma unroll
                for (int k = 0; k < 4; k++) {
                    int c = cbase + k;
                    if (c >= B.x && c < B.z) {
                        eb += E[k];
                        if (rowInt && c > B.x && c < B.z - 1) fb += F[k];
                        else fb += maskedF(sV, sT, sG, ty, 4*tx + 4 + k, r, c, B);
                    }
                }
            }
            fb = wsum(fb); eb = wsum(eb);
            if (tx == 0) { atomicAdd(&sAF[b], fb); atomicAdd(&sAE[b], eb); }
        }
    }

    // Block-staged li/lg reduce: ONE global atomic per block per counter.
    li = wsum(li); lg = wsum(lg);
    if (tx == 0) { redIn[ty] = li; redGr[ty] = lg; }
    __syncthreads();
    if (tid == 0) {
        float a = 0.f, bb = 0.f;
        #pragma unroll
        for (int i = 0; i < 8; i++) { a += redIn[i]; bb += redGr[i]; }
        atomicAdd(&d_accIn[bz],  a);
        atomicAdd(&d_accGrad[bz], bb);
    }
    if (tid < nOv) {
        atomicAdd(&d_boxF[sBoxIdx[tid]], sAF[tid]);
        atomicAdd(&d_boxE[sBoxIdx[tid]], sAE[tid]);
    }

    // Last-block finalize
    __threadfence();
    __syncthreads();
    if (tid == 0) {
        unsigned o = atomicAdd(&d_count, 1u);
        sIsLast = (o == NBLOCKS - 1);
    }
    __syncthreads();
    if (!sIsLast) return;

    if (tid < BATCH * NLAB) {
        const int* L = label + tid * 5;
        int x1 = L[1], y1 = L[2], x2 = L[3], y2 = L[4];
        bool valid = !(x1 == 0 && y1 == 0 && x2 == 0 && y2 == 0);
        float area = (float)((y2 - y1) * (x2 - x1));       // C == 1
        float sa = fmaxf(area, 1.f);
        volatile float* vF = (volatile float*)d_boxF;
        volatile float* vE = (volatile float*)d_boxE;
        float f = vF[tid], e = vE[tid];
        float vv = valid ? 1.f : 0.f;
        sLs[tid] = (f / sa) * vv;
        sL1[tid] = (e / sa) * vv;
        d_boxF[tid] = 0.f; d_boxE[tid] = 0.f;              // reset for next replay
    }
    __syncthreads();
    if (tid < BATCH) {
        volatile float* aI = (volatile float*)d_accIn;
        volatile float* aG = (volatile float*)d_accGrad;
        const float inv = 1.0f / (float)NPIX;              // C == 1
        float loss_in   = aI[tid] * inv;
        float loss_grad = aG[tid] * inv;
        d_accIn[tid] = 0.f; d_accGrad[tid] = 0.f;          // reset

        float sLsum = 0.f, s1sum = 0.f, cnt = 0.f;
        for (int n = 0; n < NLAB; n++) {
            float a = sLs[tid * NLAB + n], bb = sL1[tid * NLAB + n];
            sLsum += a; s1sum += bb;
            if (a != 0.f || bb != 0.f) cnt += 1.f;
        }
        float safe_cnt = fmaxf(cnt, 1.f);
        float ls  = (cnt > 0.f) ? sLsum / safe_cnt : 0.f;
        float lin = (cnt > 0.f) ? s1sum / safe_cnt : 0.f;
        float alpha = *bptr, beta = *cptr;
        out[0*BATCH + tid] = 0.f;                                         // loss_ss
        out[1*BATCH + tid] = alpha * loss_in + (1.f - alpha) * loss_grad; // loss_global
        out[2*BATCH + tid] = (1.f - beta) * ls + beta * lin;              // loss_label
        out[3*BATCH + tid] = loss_in;
        out[4*BATCH + tid] = loss_grad;
        out[5*BATCH + tid] = ls;
        out[6*BATCH + tid] = lin;
    }
    if (tid == 0) d_count = 0;                                            // reset
}

extern "C" void kernel_launch(void* const* d_in, const int* in_sizes, int n_in,
                              void* d_out, int out_size)
{
    (void)in_sizes; (void)n_in; (void)out_size;
    const float* bptr  = (const float*)d_in[0];
    const float* cptr  = (const float*)d_in[1];
    const float* vis   = (const float*)d_in[2];
    // d_in[3] = image_ir (unused by the reference)
    const float* gen   = (const float*)d_in[4];
    const int*   label = (const int*)d_in[5];
    const float* th    = (const float*)d_in[6];
    float* out = (float*)d_out;

    dim3 grid(GXB, GYB, BATCH);
    dim3 blk(32, 8);
    fused_k<<<grid, blk>>>(vis, th, gen, label, bptr, cptr, out);
}

// round 12
// speedup vs baseline: 1.6177x; 1.0859x over previous
#include <cuda_runtime.h>
#include <cstdint>

#define HH    640
#define WW    640
#define BATCH 4
#define NLAB  10
#define NPIX  (HH*WW)
#define TILE_W 128
#define TILE_H 8
#define GXB (WW/TILE_W)            // 5
#define GYB (HH/TILE_H)            // 80
#define NBLOCKS (GXB*GYB*BATCH)    // 1600
#define SMW 136                    // smem row width (floats): 4 left halo + 128 + 1 right (+pad); rows 16B-aligned
#define HROWS (TILE_H+2)           // 10
#define ITEMS_PER_ARR (HROWS*34)   // 340 float4 items
#define ITEMS_TOTAL (3*ITEMS_PER_ARR) // 1020

__device__ float d_accIn[BATCH];
__device__ float d_accGrad[BATCH];
__device__ float d_boxF[BATCH*NLAB];
__device__ float d_boxE[BATCH*NLAB];
__device__ unsigned d_count;

__device__ __forceinline__ float wsum(float v) {
    #pragma unroll
    for (int o = 16; o; o >>= 1) v += __shfl_down_sync(0xffffffffu, v, o);
    return v;
}

__device__ __forceinline__ void cpasync16(uint32_t saddr, const float* g, bool pred) {
    int sz = pred ? 16 : 0;
    asm volatile("cp.async.ca.shared.global [%0], [%1], 16, %2;\n"
                 :: "r"(saddr), "l"(g), "r"(sz));
}

struct G4 { float gx[4], gy[4], c[4]; };

// Separable sobel, 6 live values per row: scalar LDS for pm1/p4, aligned LDS.128 for p0..p3.
// Center pixel k of thread tx lives at smem col 4tx+4+k.
__device__ __forceinline__ G4 sobel4(const float sm[HROWS][SMW], int ty, int tx) {
    G4 o;
    float t1[3][4], t2[3][4];
    #pragma unroll
    for (int r = 0; r < 3; r++) {
        const float* row = &sm[ty + r][0];
        float  pm1 = row[4*tx + 3];                                    // LDS.32, conflict-free
        float4 M   = *reinterpret_cast<const float4*>(row + 4*tx + 4); // LDS.128 aligned
        float  p4  = row[4*tx + 8];                                    // LDS.32, conflict-free
        float p0 = M.x, p1 = M.y, p2 = M.z, p3 = M.w;
        t1[r][0] = pm1 + 2.f*p0 + p1;  t1[r][1] = p0 + 2.f*p1 + p2;
        t1[r][2] = p1 + 2.f*p2 + p3;   t1[r][3] = p2 + 2.f*p3 + p4;
        t2[r][0] = p1 - pm1;  t2[r][1] = p2 - p0;  t2[r][2] = p3 - p1;  t2[r][3] = p4 - p2;
        if (r == 1) { o.c[0] = p0; o.c[1] = p1; o.c[2] = p2; o.c[3] = p3; }
    }
    #pragma unroll
    for (int k = 0; k < 4; k++) {
        o.gx[k] = t2[0][k] + 2.f*t2[1][k] + t2[2][k];
        o.gy[k] = t1[0][k] - t1[2][k];
    }
    return o;
}

// Exact masked sobel F at a ring pixel from the shared tiles. lcc = 4tx+4+k.
__device__ float maskedF(const float sV[HROWS][SMW], const float sT[HROWS][SMW],
                         const float sG[HROWS][SMW], int ty, int lcc,
                         int r, int c, int4 B)
{
    const float wx[3][3] = {{-1,0,1},{-2,0,2},{-1,0,1}};
    const float wy[3][3] = {{1,2,1},{0,0,0},{-1,-2,-1}};
    float gxV=0,gyV=0,gxT=0,gyT=0,gxG=0,gyG=0;
    #pragma unroll
    for (int dr = 0; dr < 3; dr++)
    #pragma unroll
    for (int dc = 0; dc < 3; dc++) {
        int rr = r + dr - 1, cc = c + dc - 1;
        bool in = (rr >= B.y) & (rr < B.w) & (cc >= B.x) & (cc < B.z);
        float m = in ? 1.f : 0.f;
        float fv = sV[ty + dr][lcc - 1 + dc] * m;
        float ft = sT[ty + dr][lcc - 1 + dc] * m;
        float fg = sG[ty + dr][lcc - 1 + dc] * m;
        gxV += wx[dr][dc] * fv; gyV += wy[dr][dc] * fv;
        gxT += wx[dr][dc] * ft; gyT += wy[dr][dc] * ft;
        gxG += wx[dr][dc] * fg; gyG += wy[dr][dc] * fg;
    }
    float gradV = fabsf(gxV) + fabsf(gyV);
    float grad7 = fabsf(0.3f*gxV + 0.7f*gxT) + fabsf(0.3f*gyV + 0.7f*gyT);
    float gradG = fabsf(gxG) + fabsf(gyG);
    return fabsf(gradG - fmaxf(gradV, grad7));
}

__global__ __launch_bounds__(256, 4) void fused_k(
    const float* __restrict__ vis, const float* __restrict__ th,
    const float* __restrict__ gen, const int* __restrict__ label,
    const float* __restrict__ bptr, const float* __restrict__ cptr,
    float* __restrict__ out)
{
    __shared__ __align__(16) float sAll[3][HROWS][SMW];
    __shared__ int4  sBox[NLAB];
    __shared__ int   sBoxIdx[NLAB];
    __shared__ float sAF[NLAB], sAE[NLAB];
    __shared__ int   sN;
    __shared__ float redIn[8], redGr[8];
    __shared__ int   sIsLast;
    __shared__ float sLs[BATCH*NLAB], sL1[BATCH*NLAB];

    const int tx = threadIdx.x, ty = threadIdx.y;
    const int tid = ty * 32 + tx;
    const int bz = blockIdx.z;
    const int colStart = blockIdx.x * TILE_W;
    const int rowStart = blockIdx.y * TILE_H;
    const int base = bz * NPIX;

    const float* arrs[3] = { vis, th, gen };

    // Async halo: 1020 aligned 16B copies (zero-fill outside the image).
    #pragma unroll
    for (int s = 0; s < 4; s++) {
        int item = tid + 256 * s;
        if (item < ITEMS_TOTAL) {
            int arr = item / ITEMS_PER_ARR;
            int rem = item - arr * ITEMS_PER_ARR;
            int lr = rem / 34, j = rem - lr * 34;
            int gr = rowStart - 1 + lr;
            int gc0 = colStart - 4 + 4 * j;
            bool in = (gr >= 0) & (gr < HH) & (gc0 >= 0) & (gc0 < WW);
            const float* g = arrs[arr] + (in ? base + gr * WW + gc0 : base);
            uint32_t sa = (uint32_t)__cvta_generic_to_shared(&sAll[arr][lr][4 * j]);
            cpasync16(sa, g, in);
        }
    }
    asm volatile("cp.async.commit_group;\n");

    // Warp 0 builds the overlapping-box list while copies are in flight.
    if (tid < 32) {
        if (tid == 0) sN = 0;
        if (tid < NLAB) { sAF[tid] = 0.f; sAE[tid] = 0.f; }
        __syncwarp();
        if (tid < NLAB) {
            const int* L = label + (bz * NLAB + tid) * 5;
            int x1 = L[1], y1 = L[2], x2 = L[3], y2 = L[4];
            if (x2 > x1 && y2 > y1 &&
                x1 < colStart + TILE_W && x2 > colStart &&
                y1 < rowStart + TILE_H && y2 > rowStart) {
                int p = atomicAdd(&sN, 1);
                sBox[p] = make_int4(x1, y1, x2, y2);
                sBoxIdx[p] = bz * NLAB + tid;
            }
        }
    }

    asm volatile("cp.async.wait_group 0;\n");
    __syncthreads();
    const int nOv = sN;

    typedef const float (*Tile)[SMW];
    Tile sV = sAll[0], sT = sAll[1], sG = sAll[2];

    G4 gv = sobel4(sAll[0], ty, tx);
    G4 gt = sobel4(sAll[1], ty, tx);
    G4 gg = sobel4(sAll[2], ty, tx);

    float li = 0.f, lg = 0.f;
    #pragma unroll
    for (int k = 0; k < 4; k++) {
        float gradV = fabsf(gv.gx[k]) + fabsf(gv.gy[k]);
        float gradG = fabsf(gg.gx[k]) + fabsf(gg.gy[k]);
        float g5 = 0.5f * (fabsf(gv.gx[k] + gt.gx[k]) + fabsf(gv.gy[k] + gt.gy[k]));
        float xm = 0.5f * (gv.c[k] + gt.c[k]);
        li += fabsf(gg.c[k] - fmaxf(gv.c[k], xm));
        lg += fabsf(gradG - fmaxf(gradV, g5));
    }

    if (nOv > 0) {
        float F[4], E[4];
        #pragma unroll
        for (int k = 0; k < 4; k++) {
            float gradV = fabsf(gv.gx[k]) + fabsf(gv.gy[k]);
            float gradG = fabsf(gg.gx[k]) + fabsf(gg.gy[k]);
            float g7 = fabsf(0.3f*gv.gx[k] + 0.7f*gt.gx[k]) + fabsf(0.3f*gv.gy[k] + 0.7f*gt.gy[k]);
            float xm7 = 0.3f * gv.c[k] + 0.7f * gt.c[k];
            F[k] = fabsf(gradG - fmaxf(gradV, g7));
            E[k] = fabsf(gg.c[k] - fmaxf(gv.c[k], xm7));
        }
        const int r = rowStart + ty;
        const int cbase = colStart + tx * 4;
        for (int b = 0; b < nOv; b++) {
            int4 B = sBox[b];
            float fb = 0.f, eb = 0.f;
            if (r >= B.y && r < B.w) {
                bool rowInt = (r > B.y) & (r < B.w - 1);
                #pragma unroll
                for (int k = 0; k < 4; k++) {
                    int c = cbase + k;
                    if (c >= B.x && c < B.z) {
                        eb += E[k];
                        if (rowInt && c > B.x && c < B.z - 1) fb += F[k];
                        else fb += maskedF(sV, sT, sG, ty, 4*tx + 4 + k, r, c, B);
                    }
                }
            }
            fb = wsum(fb); eb = wsum(eb);
            if (tx == 0) { atomicAdd(&sAF[b], fb); atomicAdd(&sAE[b], eb); }
        }
    }

    // Block-staged li/lg reduce: ONE global atomic per block per counter.
    li = wsum(li); lg = wsum(lg);
    if (tx == 0) { redIn[ty] = li; redGr[ty] = lg; }
    __syncthreads();
    if (tid == 0) {
        float a = 0.f, bb = 0.f;
        #pragma unroll
        for (int i = 0; i < 8; i++) { a += redIn[i]; bb += redGr[i]; }
        atomicAdd(&d_accIn[bz],  a);
        atomicAdd(&d_accGrad[bz], bb);
    }
    if (tid < nOv) {
        atomicAdd(&d_boxF[sBoxIdx[tid]], sAF[tid]);
        atomicAdd(&d_boxE[sBoxIdx[tid]], sAE[tid]);
    }

    // Last-block finalize
    __threadfence();
    __syncthreads();
    if (tid == 0) {
        unsigned o = atomicAdd(&d_count, 1u);
        sIsLast = (o == NBLOCKS - 1);
    }
    __syncthreads();
    if (!sIsLast) return;

    if (tid < BATCH * NLAB) {
        const int* L = label + tid * 5;
        int x1 = L[1], y1 = L[2], x2 = L[3], y2 = L[4];
        bool valid = !(x1 == 0 && y1 == 0 && x2 == 0 && y2 == 0);
        float area = (float)((y2 - y1) * (x2 - x1));       // C == 1
        float sa = fmaxf(area, 1.f);
        volatile float* vF = (volatile float*)d_boxF;
        volatile float* vE = (volatile float*)d_boxE;
        float f = vF[tid], e = vE[tid];
        float vv = valid ? 1.f : 0.f;
        sLs[tid] = (f / sa) * vv;
        sL1[tid] = (e / sa) * vv;
        d_boxF[tid] = 0.f; d_boxE[tid] = 0.f;              // reset for next replay
    }
    __syncthreads();
    if (tid < BATCH) {
        volatile float* aI = (volatile float*)d_accIn;
        volatile float* aG = (volatile float*)d_accGrad;
        const float inv = 1.0f / (float)NPIX;              // C == 1
        float loss_in   = aI[tid] * inv;
        float loss_grad = aG[tid] * inv;
        d_accIn[tid] = 0.f; d_accGrad[tid] = 0.f;          // reset

        float sLsum = 0.f, s1sum = 0.f, cnt = 0.f;
        for (int n = 0; n < NLAB; n++) {
            float a = sLs[tid * NLAB + n], bb = sL1[tid * NLAB + n];
            sLsum += a; s1sum += bb;
            if (a != 0.f || bb != 0.f) cnt += 1.f;
        }
        float safe_cnt = fmaxf(cnt, 1.f);
        float ls  = (cnt > 0.f) ? sLsum / safe_cnt : 0.f;
        float lin = (cnt > 0.f) ? s1sum / safe_cnt : 0.f;
        float alpha = *bptr, beta = *cptr;
        out[0*BATCH + tid] = 0.f;                                         // loss_ss
        out[1*BATCH + tid] = alpha * loss_in + (1.f - alpha) * loss_grad; // loss_global
        out[2*BATCH + tid] = (1.f - beta) * ls + beta * lin;              // loss_label
        out[3*BATCH + tid] = loss_in;
        out[4*BATCH + tid] = loss_grad;
        out[5*BATCH + tid] = ls;
        out[6*BATCH + tid] = lin;
    }
    if (tid == 0) d_count = 0;                                            // reset
}

extern "C" void kernel_launch(void* const* d_in, const int* in_sizes, int n_in,
                              void* d_out, int out_size)
{
    (void)in_sizes; (void)n_in; (void)out_size;
    const float* bptr  = (const float*)d_in[0];
    const float* cptr  = (const float*)d_in[1];
    const float* vis   = (const float*)d_in[2];
    // d_in[3] = image_ir (unused by the reference)
    const float* gen   = (const float*)d_in[4];
    const int*   label = (const int*)d_in[5];
    const float* th    = (const float*)d_in[6];
    float* out = (float*)d_out;

    dim3 grid(GXB, GYB, BATCH);
    dim3 blk(32, 8);
    fused_k<<<grid, blk>>>(vis, th, gen, label, bptr, cptr, out);
}

// round 13
// speedup vs baseline: 1.6267x; 1.0056x over previous
#include <cuda_runtime.h>
#include <cstdint>

#define HH    640
#define WW    640
#define BATCH 4
#define NLAB  10
#define NPIX  (HH*WW)
#define TILE_W 128
#define TILE_H 8
#define GXB (WW/TILE_W)            // 5
#define GYB (HH/TILE_H)            // 80
#define NBLOCKS (GXB*GYB*BATCH)    // 1600
#define SMW 136                    // smem row width (floats): 4 left halo + 128 + 1 right (+pad); rows 16B-aligned
#define HROWS (TILE_H+2)           // 10
#define ITEMS_PER_ARR (HROWS*34)   // 340 float4 items
#define ITEMS_TOTAL (3*ITEMS_PER_ARR) // 1020

__device__ float d_accIn[BATCH];
__device__ float d_accGrad[BATCH];
__device__ float d_boxF[BATCH*NLAB];
__device__ float d_boxE[BATCH*NLAB];
__device__ unsigned d_count;

__device__ __forceinline__ float wsum(float v) {
    #pragma unroll
    for (int o = 16; o; o >>= 1) v += __shfl_down_sync(0xffffffffu, v, o);
    return v;
}

__device__ __forceinline__ void cpasync16(uint32_t saddr, const float* g, bool pred) {
    int sz = pred ? 16 : 0;
    asm volatile("cp.async.ca.shared.global [%0], [%1], 16, %2;\n"
                 :: "r"(saddr), "l"(g), "r"(sz));
}

struct G4 { float gx[4], gy[4], c[4]; };

// Separable sobel, 6 live values per row. Center pixel k of thread tx at smem col 4tx+4+k.
// NOTE: middle-row smoothing (t1[1]) is never needed (gy = t1[0]-t1[2]) -> not computed.
__device__ __forceinline__ G4 sobel4(const float sm[HROWS][SMW], int ty, int tx) {
    G4 o;
    float t1a[4], t1c[4];      // smoothing of top & bottom rows
    float t2[3][4];            // horizontal diffs of all 3 rows
    #pragma unroll
    for (int r = 0; r < 3; r++) {
        const float* row = &sm[ty + r][0];
        float  pm1 = row[4*tx + 3];                                    // LDS.32, conflict-free
        float4 M   = *reinterpret_cast<const float4*>(row + 4*tx + 4); // LDS.128 aligned
        float  p4  = row[4*tx + 8];                                    // LDS.32, conflict-free
        float p0 = M.x, p1 = M.y, p2 = M.z, p3 = M.w;
        t2[r][0] = p1 - pm1;  t2[r][1] = p2 - p0;  t2[r][2] = p3 - p1;  t2[r][3] = p4 - p2;
        if (r == 0) {
            t1a[0] = pm1 + 2.f*p0 + p1;  t1a[1] = p0 + 2.f*p1 + p2;
            t1a[2] = p1 + 2.f*p2 + p3;   t1a[3] = p2 + 2.f*p3 + p4;
        } else if (r == 1) {
            o.c[0] = p0; o.c[1] = p1; o.c[2] = p2; o.c[3] = p3;
        } else {
            t1c[0] = pm1 + 2.f*p0 + p1;  t1c[1] = p0 + 2.f*p1 + p2;
            t1c[2] = p1 + 2.f*p2 + p3;   t1c[3] = p2 + 2.f*p3 + p4;
        }
    }
    #pragma unroll
    for (int k = 0; k < 4; k++) {
        o.gx[k] = t2[0][k] + 2.f*t2[1][k] + t2[2][k];
        o.gy[k] = t1a[k] - t1c[k];
    }
    return o;
}

// Exact masked sobel F at a ring pixel from the shared tiles. lcc = 4tx+4+k.
__device__ float maskedF(const float sV[HROWS][SMW], const float sT[HROWS][SMW],
                         const float sG[HROWS][SMW], int ty, int lcc,
                         int r, int c, int4 B)
{
    const float wx[3][3] = {{-1,0,1},{-2,0,2},{-1,0,1}};
    const float wy[3][3] = {{1,2,1},{0,0,0},{-1,-2,-1}};
    float gxV=0,gyV=0,gxT=0,gyT=0,gxG=0,gyG=0;
    #pragma unroll
    for (int dr = 0; dr < 3; dr++)
    #pragma unroll
    for (int dc = 0; dc < 3; dc++) {
        int rr = r + dr - 1, cc = c + dc - 1;
        bool in = (rr >= B.y) & (rr < B.w) & (cc >= B.x) & (cc < B.z);
        float m = in ? 1.f : 0.f;
        float fv = sV[ty + dr][lcc - 1 + dc] * m;
        float ft = sT[ty + dr][lcc - 1 + dc] * m;
        float fg = sG[ty + dr][lcc - 1 + dc] * m;
        gxV += wx[dr][dc] * fv; gyV += wy[dr][dc] * fv;
        gxT += wx[dr][dc] * ft; gyT += wy[dr][dc] * ft;
        gxG += wx[dr][dc] * fg; gyG += wy[dr][dc] * fg;
    }
    float gradV = fabsf(gxV) + fabsf(gyV);
    float grad7 = fabsf(0.3f*gxV + 0.7f*gxT) + fabsf(0.3f*gyV + 0.7f*gyT);
    float gradG = fabsf(gxG) + fabsf(gyG);
    return fabsf(gradG - fmaxf(gradV, grad7));
}

__global__ __launch_bounds__(256, 4) void fused_k(
    const float* __restrict__ vis, const float* __restrict__ th,
    const float* __restrict__ gen, const int* __restrict__ label,
    const float* __restrict__ bptr, const float* __restrict__ cptr,
    float* __restrict__ out)
{
    __shared__ __align__(16) float sAll[3][HROWS][SMW];
    __shared__ int4  sBox[NLAB];
    __shared__ int   sBoxIdx[NLAB];
    __shared__ float sAF[NLAB], sAE[NLAB];
    __shared__ int   sN;
    __shared__ float redIn[8], redGr[8];
    __shared__ int   sIsLast;
    __shared__ float sLs[BATCH*NLAB], sL1[BATCH*NLAB];

    const int tx = threadIdx.x, ty = threadIdx.y;
    const int tid = ty * 32 + tx;
    const int bz = blockIdx.z;
    const int colStart = blockIdx.x * TILE_W;
    const int rowStart = blockIdx.y * TILE_H;
    const int base = bz * NPIX;

    // Async halo: 1020 aligned 16B copies (zero-fill outside the image).
    #pragma unroll
    for (int s = 0; s < 4; s++) {
        int item = tid + 256 * s;
        if (item < ITEMS_TOTAL) {
            int arr = item / ITEMS_PER_ARR;
            int rem = item - arr * ITEMS_PER_ARR;
            int lr = rem / 34, j = rem - lr * 34;
            int gr = rowStart - 1 + lr;
            int gc0 = colStart - 4 + 4 * j;
            bool in = (gr >= 0) & (gr < HH) & (gc0 >= 0) & (gc0 < WW);
            const float* src = (arr == 0) ? vis : (arr == 1) ? th : gen;  // SELs, no LMEM
            const float* g = src + (in ? base + gr * WW + gc0 : base);
            uint32_t sa = (uint32_t)__cvta_generic_to_shared(&sAll[arr][lr][4 * j]);
            cpasync16(sa, g, in);
        }
    }
    asm volatile("cp.async.commit_group;\n");

    // Warp 0 builds the overlapping-box list while copies are in flight.
    if (tid < 32) {
        if (tid == 0) sN = 0;
        if (tid < NLAB) { sAF[tid] = 0.f; sAE[tid] = 0.f; }
        __syncwarp();
        if (tid < NLAB) {
            const int* L = label + (bz * NLAB + tid) * 5;
            int x1 = L[1], y1 = L[2], x2 = L[3], y2 = L[4];
            if (x2 > x1 && y2 > y1 &&
                x1 < colStart + TILE_W && x2 > colStart &&
                y1 < rowStart + TILE_H && y2 > rowStart) {
                int p = atomicAdd(&sN, 1);
                sBox[p] = make_int4(x1, y1, x2, y2);
                sBoxIdx[p] = bz * NLAB + tid;
            }
        }
    }

    asm volatile("cp.async.wait_group 0;\n");
    __syncthreads();
    const int nOv = sN;

    typedef const float (*Tile)[SMW];
    Tile sV = sAll[0], sT = sAll[1], sG = sAll[2];

    G4 gv = sobel4(sAll[0], ty, tx);
    G4 gt = sobel4(sAll[1], ty, tx);
    G4 gg = sobel4(sAll[2], ty, tx);

    float li = 0.f, lg = 0.f;
    if (nOv == 0) {
        // Common path: only the global losses.
        #pragma unroll
        for (int k = 0; k < 4; k++) {
            float gradV = fabsf(gv.gx[k]) + fabsf(gv.gy[k]);
            float gradG = fabsf(gg.gx[k]) + fabsf(gg.gy[k]);
            float g5 = 0.5f * (fabsf(gv.gx[k] + gt.gx[k]) + fabsf(gv.gy[k] + gt.gy[k]));
            float xm = 0.5f * (gv.c[k] + gt.c[k]);
            li += fabsf(gg.c[k] - fmaxf(gv.c[k], xm));
            lg += fabsf(gradG - fmaxf(gradV, g5));
        }
    } else {
        // Box path: single loop computes everything (no duplicate gradV/gradG).
        float F[4], E[4];
        #pragma unroll
        for (int k = 0; k < 4; k++) {
            float gradV = fabsf(gv.gx[k]) + fabsf(gv.gy[k]);
            float gradG = fabsf(gg.gx[k]) + fabsf(gg.gy[k]);
            float g5 = 0.5f * (fabsf(gv.gx[k] + gt.gx[k]) + fabsf(gv.gy[k] + gt.gy[k]));
            float g7 = fabsf(0.3f*gv.gx[k] + 0.7f*gt.gx[k]) + fabsf(0.3f*gv.gy[k] + 0.7f*gt.gy[k]);
            float xm  = 0.5f * (gv.c[k] + gt.c[k]);
            float xm7 = 0.3f * gv.c[k] + 0.7f * gt.c[k];
            li += fabsf(gg.c[k] - fmaxf(gv.c[k], xm));
            lg += fabsf(gradG - fmaxf(gradV, g5));
            F[k] = fabsf(gradG - fmaxf(gradV, g7));
            E[k] = fabsf(gg.c[k] - fmaxf(gv.c[k], xm7));
        }
        const int r = rowStart + ty;
        const int cbase = colStart + tx * 4;
        for (int b = 0; b < nOv; b++) {
            int4 B = sBox[b];
            float fb = 0.f, eb = 0.f;
            if (r >= B.y && r < B.w) {
                bool rowInt = (r > B.y) & (r < B.w - 1);
                #pragma unroll
                for (int k = 0; k < 4; k++) {
                    int c = cbase + k;
                    if (c >= B.x && c < B.z) {
                        eb += E[k];
                        if (rowInt && c > B.x && c < B.z - 1) fb += F[k];
                        else fb += maskedF(sV, sT, sG, ty, 4*tx + 4 + k, r, c, B);
                    }
                }
            }
            fb = wsum(fb); eb = wsum(eb);
            if (tx == 0) { atomicAdd(&sAF[b], fb); atomicAdd(&sAE[b], eb); }
        }
    }

    // Block-staged li/lg reduce: ONE global atomic per block per counter.
    li = wsum(li); lg = wsum(lg);
    if (tx == 0) { redIn[ty] = li; redGr[ty] = lg; }
    __syncthreads();
    if (tid == 0) {
        float a = 0.f, bb = 0.f;
        #pragma unroll
        for (int i = 0; i < 8; i++) { a += redIn[i]; bb += redGr[i]; }
        atomicAdd(&d_accIn[bz],  a);
        atomicAdd(&d_accGrad[bz], bb);
    }
    if (tid < nOv) {
        atomicAdd(&d_boxF[sBoxIdx[tid]], sAF[tid]);
        atomicAdd(&d_boxE[sBoxIdx[tid]], sAE[tid]);
    }

    // Last-block finalize
    __threadfence();
    __syncthreads();
    if (tid == 0) {
        unsigned o = atomicAdd(&d_count, 1u);
        sIsLast = (o == NBLOCKS - 1);
    }
    __syncthreads();
    if (!sIsLast) return;

    if (tid < BATCH * NLAB) {
        const int* L = label + tid * 5;
        int x1 = L[1], y1 = L[2], x2 = L[3], y2 = L[4];
        bool valid = !(x1 == 0 && y1 == 0 && x2 == 0 && y2 == 0);
        float area = (float)((y2 - y1) * (x2 - x1));       // C == 1
        float sa = fmaxf(area, 1.f);
        volatile float* vF = (volatile float*)d_boxF;
        volatile float* vE = (volatile float*)d_boxE;
        float f = vF[tid], e = vE[tid];
        float vv = valid ? 1.f : 0.f;
        sLs[tid] = (f / sa) * vv;
        sL1[tid] = (e / sa) * vv;
        d_boxF[tid] = 0.f; d_boxE[tid] = 0.f;              // reset for next replay
    }
    __syncthreads();
    if (tid < BATCH) {
        volatile float* aI = (volatile float*)d_accIn;
        volatile float* aG = (volatile float*)d_accGrad;
        const float inv = 1.0f / (float)NPIX;              // C == 1
        float loss_in   = aI[tid] * inv;
        float loss_grad = aG[tid] * inv;
        d_accIn[tid] = 0.f; d_accGrad[tid] = 0.f;          // reset

        float sLsum = 0.f, s1sum = 0.f, cnt = 0.f;
        for (int n = 0; n < NLAB; n++) {
            float a = sLs[tid * NLAB + n], bb = sL1[tid * NLAB + n];
            sLsum += a; s1sum += bb;
            if (a != 0.f || bb != 0.f) cnt += 1.f;
        }
        float safe_cnt = fmaxf(cnt, 1.f);
        float ls  = (cnt > 0.f) ? sLsum / safe_cnt : 0.f;
        float lin = (cnt > 0.f) ? s1sum / safe_cnt : 0.f;
        float alpha = *bptr, beta = *cptr;
        out[0*BATCH + tid] = 0.f;                                         // loss_ss
        out[1*BATCH + tid] = alpha * loss_in + (1.f - alpha) * loss_grad; // loss_global
        out[2*BATCH + tid] = (1.f - beta) * ls + beta * lin;              // loss_label
        out[3*BATCH + tid] = loss_in;
        out[4*BATCH + tid] = loss_grad;
        out[5*BATCH + tid] = ls;
        out[6*BATCH + tid] = lin;
    }
    if (tid == 0) d_count = 0;                                            // reset
}

extern "C" void kernel_launch(void* const* d_in, const int* in_sizes, int n_in,
                              void* d_out, int out_size)
{
    (void)in_sizes; (void)n_in; (void)out_size;
    const float* bptr  = (const float*)d_in[0];
    const float* cptr  = (const float*)d_in[1];
    const float* vis   = (const float*)d_in[2];
    // d_in[3] = image_ir (unused by the reference)
    const float* gen   = (const float*)d_in[4];
    const int*   label = (const int*)d_in[5];
    const float* th    = (const float*)d_in[6];
    float* out = (float*)d_out;

    dim3 grid(GXB, GYB, BATCH);
    dim3 blk(32, 8);
    fused_k<<<grid, blk>>>(vis, th, gen, label, bptr, cptr, out);
}